// round 1
// baseline (speedup 1.0000x reference)
#include <cuda_runtime.h>
#include <cuda_bf16.h>
#include <cfloat>

#define LEVELS 255.0f
#define EPS 1e-8f

// One CTA per row (channel). Row = 16384 fp32 = 4096 float4.
// 1024 threads * 4 float4 each = full row held in registers.
// Pass 1 (in-register): min/max block reduction.
// Pass 2 (in-register): quantize + store. x is read from HBM exactly once.

__global__ __launch_bounds__(1024, 1)
void perchannel_quant_kernel(const float* __restrict__ x,
                             float* __restrict__ out,
                             int row_len_vec4)   // 4096
{
    const int row = blockIdx.x;
    const int tid = threadIdx.x;

    const float4* __restrict__ xrow =
        reinterpret_cast<const float4*>(x) + (size_t)row * row_len_vec4;
    float4* __restrict__ orow =
        reinterpret_cast<float4*>(out) + (size_t)row * row_len_vec4;

    // ---- load 4 float4 per thread into registers, coalesced ----
    float4 v0 = xrow[tid];
    float4 v1 = xrow[tid + 1024];
    float4 v2 = xrow[tid + 2048];
    float4 v3 = xrow[tid + 3072];

    // ---- per-thread min/max ----
    float mn = fminf(fminf(fminf(v0.x, v0.y), fminf(v0.z, v0.w)),
                     fminf(fminf(v1.x, v1.y), fminf(v1.z, v1.w)));
    float mx = fmaxf(fmaxf(fmaxf(v0.x, v0.y), fmaxf(v0.z, v0.w)),
                     fmaxf(fmaxf(v1.x, v1.y), fmaxf(v1.z, v1.w)));
    mn = fminf(mn, fminf(fminf(fminf(v2.x, v2.y), fminf(v2.z, v2.w)),
                         fminf(fminf(v3.x, v3.y), fminf(v3.z, v3.w))));
    mx = fmaxf(mx, fmaxf(fmaxf(fmaxf(v2.x, v2.y), fmaxf(v2.z, v2.w)),
                         fmaxf(fmaxf(v3.x, v3.y), fmaxf(v3.z, v3.w))));

    // ---- warp reduce ----
    #pragma unroll
    for (int off = 16; off > 0; off >>= 1) {
        mn = fminf(mn, __shfl_xor_sync(0xffffffffu, mn, off));
        mx = fmaxf(mx, __shfl_xor_sync(0xffffffffu, mx, off));
    }

    // ---- block reduce across 32 warps ----
    __shared__ float smn[32];
    __shared__ float smx[32];
    __shared__ float s_scale, s_inv_scale, s_zero;

    const int lane = tid & 31;
    const int wid  = tid >> 5;
    if (lane == 0) { smn[wid] = mn; smx[wid] = mx; }
    __syncthreads();

    if (wid == 0) {
        mn = smn[lane];
        mx = smx[lane];
        #pragma unroll
        for (int off = 16; off > 0; off >>= 1) {
            mn = fminf(mn, __shfl_xor_sync(0xffffffffu, mn, off));
            mx = fmaxf(mx, __shfl_xor_sync(0xffffffffu, mx, off));
        }
        if (lane == 0) {
            float x_min = fminf(mn, 0.0f);
            float x_max = fmaxf(mx, 0.0f);
            float scale = fmaxf((x_max - x_min) / LEVELS, EPS);
            float zero  = rintf(-x_min / scale);
            s_scale     = scale;
            s_inv_scale = 1.0f / scale;
            s_zero      = zero;
        }
    }
    __syncthreads();

    const float scale     = s_scale;
    const float inv_scale = s_inv_scale;
    const float zero      = s_zero;

    // ---- quantize from registers, store ----
    #define QUANT(e) do { \
        float q = rintf((e) * inv_scale) + zero; \
        q = fminf(fmaxf(q, 0.0f), LEVELS); \
        (e) = (q - zero) * scale; \
    } while (0)

    QUANT(v0.x); QUANT(v0.y); QUANT(v0.z); QUANT(v0.w);
    QUANT(v1.x); QUANT(v1.y); QUANT(v1.z); QUANT(v1.w);
    QUANT(v2.x); QUANT(v2.y); QUANT(v2.z); QUANT(v2.w);
    QUANT(v3.x); QUANT(v3.y); QUANT(v3.z); QUANT(v3.w);
    #undef QUANT

    orow[tid]        = v0;
    orow[tid + 1024] = v1;
    orow[tid + 2048] = v2;
    orow[tid + 3072] = v3;
}

extern "C" void kernel_launch(void* const* d_in, const int* in_sizes, int n_in,
                              void* d_out, int out_size)
{
    const float* x = (const float*)d_in[0];
    float* out = (float*)d_out;
    // 4096 rows x 16384 cols
    const int rows = 4096;
    const int row_len_vec4 = 16384 / 4;
    perchannel_quant_kernel<<<rows, 1024>>>(x, out, row_len_vec4);
}

// round 2
// speedup vs baseline: 1.0030x; 1.0030x over previous
#include <cuda_runtime.h>
#include <cuda_bf16.h>
#include <cfloat>

#define LEVELS 255.0f
#define EPS 1e-8f

// One CTA per row (channel). Row = 16384 fp32 = 4096 float4.
// 1024 threads * 4 float4 each = full row held in registers.
// Single pass over HBM: load -> block min/max reduce -> quantize -> store.
// v2: streaming cache hints (.cs) on both load and store, single barrier
// (all 32 warps redundantly reduce the 32 partials).

__global__ __launch_bounds__(1024, 2)
void perchannel_quant_kernel(const float* __restrict__ x,
                             float* __restrict__ out)
{
    const int row = blockIdx.x;
    const int tid = threadIdx.x;

    const float4* __restrict__ xrow =
        reinterpret_cast<const float4*>(x) + (size_t)row * 4096;
    float4* __restrict__ orow =
        reinterpret_cast<float4*>(out) + (size_t)row * 4096;

    // ---- load 4 float4 per thread, coalesced, evict-first ----
    float4 v0 = __ldcs(&xrow[tid]);
    float4 v1 = __ldcs(&xrow[tid + 1024]);
    float4 v2 = __ldcs(&xrow[tid + 2048]);
    float4 v3 = __ldcs(&xrow[tid + 3072]);

    // ---- per-thread min/max ----
    float mn = fminf(fminf(fminf(v0.x, v0.y), fminf(v0.z, v0.w)),
                     fminf(fminf(v1.x, v1.y), fminf(v1.z, v1.w)));
    float mx = fmaxf(fmaxf(fmaxf(v0.x, v0.y), fmaxf(v0.z, v0.w)),
                     fmaxf(fmaxf(v1.x, v1.y), fmaxf(v1.z, v1.w)));
    mn = fminf(mn, fminf(fminf(fminf(v2.x, v2.y), fminf(v2.z, v2.w)),
                         fminf(fminf(v3.x, v3.y), fminf(v3.z, v3.w))));
    mx = fmaxf(mx, fmaxf(fmaxf(fmaxf(v2.x, v2.y), fmaxf(v2.z, v2.w)),
                         fmaxf(fmaxf(v3.x, v3.y), fmaxf(v3.z, v3.w))));

    // ---- warp reduce ----
    #pragma unroll
    for (int off = 16; off > 0; off >>= 1) {
        mn = fminf(mn, __shfl_xor_sync(0xffffffffu, mn, off));
        mx = fmaxf(mx, __shfl_xor_sync(0xffffffffu, mx, off));
    }

    // ---- block reduce: partials to smem, ONE barrier, then every warp
    //      redundantly reduces all 32 partials (no second barrier). ----
    __shared__ float smn[32];
    __shared__ float smx[32];

    const int lane = tid & 31;
    const int wid  = tid >> 5;
    if (lane == 0) { smn[wid] = mn; smx[wid] = mx; }
    __syncthreads();

    mn = smn[lane];
    mx = smx[lane];
    #pragma unroll
    for (int off = 16; off > 0; off >>= 1) {
        mn = fminf(mn, __shfl_xor_sync(0xffffffffu, mn, off));
        mx = fmaxf(mx, __shfl_xor_sync(0xffffffffu, mx, off));
    }
    // butterfly leaves the full reduction in every lane of every warp

    const float x_min = fminf(mn, 0.0f);
    const float x_max = fmaxf(mx, 0.0f);
    const float scale = fmaxf((x_max - x_min) * (1.0f / LEVELS), EPS);
    const float zero  = rintf(-x_min / scale);
    const float inv_scale = 1.0f / scale;

    // ---- quantize from registers, store evict-first ----
    #define QUANT(e) do { \
        float q = rintf((e) * inv_scale) + zero; \
        q = fminf(fmaxf(q, 0.0f), LEVELS); \
        (e) = (q - zero) * scale; \
    } while (0)

    QUANT(v0.x); QUANT(v0.y); QUANT(v0.z); QUANT(v0.w);
    QUANT(v1.x); QUANT(v1.y); QUANT(v1.z); QUANT(v1.w);
    QUANT(v2.x); QUANT(v2.y); QUANT(v2.z); QUANT(v2.w);
    QUANT(v3.x); QUANT(v3.y); QUANT(v3.z); QUANT(v3.w);
    #undef QUANT

    __stcs(&orow[tid],        v0);
    __stcs(&orow[tid + 1024], v1);
    __stcs(&orow[tid + 2048], v2);
    __stcs(&orow[tid + 3072], v3);
}

extern "C" void kernel_launch(void* const* d_in, const int* in_sizes, int n_in,
                              void* d_out, int out_size)
{
    const float* x = (const float*)d_in[0];
    float* out = (float*)d_out;
    perchannel_quant_kernel<<<4096, 1024>>>(x, out);
}